// round 13
// baseline (speedup 1.0000x reference)
#include <cuda_runtime.h>
#include <cuda_fp16.h>
#include <math.h>
#include <stdint.h>

#define TN  256
#define BN  512
#define INN 128
#define MN  256
#define KC  640          // fused K: 128 x + 2*256 children
#define NW  96           // N tile: 32 m * 3 gates
#define GRID_P 296
#define SP  40           // padded smem row stride (fp16)

// dynamic smem: 2 stages * 25600B; stage: Ah 0 (10240), Bh 10240 (7680), Bl 17920 (7680)
#define STG 25600
#define DSM (2 * STG)

// -------- device scratch --------
__device__ __half g_Wchi[768 * KC];
__device__ __half g_Wclo[768 * KC];
__device__ __half g_Xhi[(size_t)TN * BN * INN];
__device__ __half g_Hhi[(size_t)TN * BN * MN];
__device__ float g_bc[768];
__device__ int   g_child0[TN * BN];
__device__ int   g_child1[TN * BN];
__device__ int   g_root[BN];
__device__ int   g_order[TN];
__device__ int   g_lvl[TN];
__device__ int   g_lvlstart[TN + 2];
__device__ int   g_numlevels;
__device__ unsigned g_barcnt;

// fast sigmoid / tanh via MUFU. rel err ~1e-6.
__device__ __forceinline__ float sigf(float x) {
    return __fdividef(1.0f, 1.0f + __expf(-x));
}
__device__ __forceinline__ float tanhfast(float x) {
    return 2.0f * __fdividef(1.0f, 1.0f + __expf(-2.0f * x)) - 1.0f;
}

__device__ __forceinline__ uint32_t smem_u32(const void* p) {
    uint32_t a;
    asm("{ .reg .u64 t; cvta.to.shared.u64 t, %1; cvt.u32.u64 %0, t; }" : "=r"(a) : "l"(p));
    return a;
}

__device__ __forceinline__ void mma16816(float* d, const uint32_t* a, const uint32_t* b) {
    asm volatile(
        "mma.sync.aligned.m16n8k16.row.col.f32.f16.f16.f32 "
        "{%0,%1,%2,%3}, {%4,%5,%6,%7}, {%8,%9}, {%0,%1,%2,%3};"
        : "+f"(d[0]), "+f"(d[1]), "+f"(d[2]), "+f"(d[3])
        : "r"(a[0]), "r"(a[1]), "r"(a[2]), "r"(a[3]), "r"(b[0]), "r"(b[1]));
}

__device__ __forceinline__ void ldsm4(uint32_t* r, uint32_t addr) {
    asm volatile("ldmatrix.sync.aligned.m8n8.x4.shared.b16 {%0,%1,%2,%3}, [%4];"
                 : "=r"(r[0]), "=r"(r[1]), "=r"(r[2]), "=r"(r[3]) : "r"(addr));
}

__device__ __forceinline__ void cpa16(uint32_t dst, const void* src, int sz) {
    asm volatile("cp.async.ca.shared.global [%0], [%1], 16, %2;"
                 :: "r"(dst), "l"(src), "r"(sz) : "memory");
}
__device__ __forceinline__ void cpa_commit() {
    asm volatile("cp.async.commit_group;" ::: "memory");
}
__device__ __forceinline__ void cpa_wait1() {
    asm volatile("cp.async.wait_group 1;" ::: "memory");
}
__device__ __forceinline__ void cpa_wait0() {
    asm volatile("cp.async.wait_group 0;" ::: "memory");
}

__device__ __forceinline__ uint32_t packh2(float x, float y) {
    __half2 v = __floats2half2_rn(x, y);
    return *reinterpret_cast<uint32_t*>(&v);
}

// -------- prep: X split (fp16 hi, lo-in-weights scheme: X hi + residual folded), weights split --------
// NOTE: 2-term scheme: value = hi + lo with hi=fp16(x), lo=fp16(x-hi).
// A side keeps ONLY hi (residual dropped at MMA level: d = Ah*Bh + Ah*Bl).
// To preserve A-side accuracy, the A residual must be small: fp16 RN gives |lo|<=2^-12|x|.
__global__ void prep_kernel(const float* __restrict__ X,
                            const float* __restrict__ Wi, const float* __restrict__ bi,
                            const float* __restrict__ Wo, const float* __restrict__ bo,
                            const float* __restrict__ Wu, const float* __restrict__ bu,
                            const float* __restrict__ Ui, const float* __restrict__ Uo,
                            const float* __restrict__ Uu) {
    size_t idx = blockIdx.x * blockDim.x + threadIdx.x;
    size_t stride = (size_t)gridDim.x * blockDim.x;
    if (idx == 0) g_barcnt = 0u;
    for (size_t i = idx; i < TN; i += stride) g_lvl[i] = 0;
    for (size_t i = idx; i < (size_t)TN * BN * INN; i += stride) {
        g_Xhi[i] = __float2half_rn(X[i]);
    }
    for (size_t i = idx; i < (size_t)768 * KC; i += stride) {
        int n = (int)(i / KC);
        int k = (int)(i % KC);
        int m = n / 3;
        int g = n % 3;
        float x;
        if (k < INN) {
            const float* W = (g == 0) ? Wi : ((g == 1) ? Wo : Wu);
            x = W[m * INN + k];
        } else {
            const float* U = (g == 0) ? Ui : ((g == 1) ? Uo : Uu);
            int br = (k - INN) / MN;
            int kk = (k - INN) % MN;
            x = U[br * MN * MN + m * MN + kk];
        }
        __half h = __float2half_rn(x);
        g_Wchi[i] = h;
        g_Wclo[i] = __float2half_rn(x - __half2float(h));
    }
    for (size_t i = idx; i < 768; i += stride) {
        int m = (int)i / 3;
        int g = (int)i % 3;
        const float* bb = (g == 0) ? bi : ((g == 1) ? bo : bu);
        g_bc[i] = bb[m];
    }
}

// -------- scheduler A: per-tree stack sim, 16 blocks x 32 trees --------
__global__ void sched_a_kernel(const int* __restrict__ arities) {
    int b = blockIdx.x * 32 + threadIdx.x;
    int stck[TN + 2];
    int lvl[TN];
    for (int i = 0; i < TN + 2; i++) stck[i] = 0;
    int sp = 1;
    for (int t = 0; t < TN; t++) {
        int a = arities[t * BN + b];
        int c0 = -1;
        int c1 = -1;
        if (a > 0) {
            int s = stck[max(sp, 0)];
            if (s < t) c0 = s;
        }
        if (a > 1) {
            int s = stck[max(sp - 1, 0)];
            if (s < t) c1 = s;
        }
        g_child0[t * BN + b] = c0;
        g_child1[t * BN + b] = c1;
        int L = 0;
        if (c0 >= 0) L = lvl[c0] + 1;
        if (c1 >= 0) L = max(L, lvl[c1] + 1);
        lvl[t] = L;
        atomicMax(&g_lvl[t], L);
        sp += 1 - abs(a);
        if (sp < 0) sp = 0;
        if (sp > TN + 1) sp = TN + 1;
        if (a != -1) stck[sp] = t;
    }
    g_root[b] = stck[max(sp, 0)];
}

// -------- scheduler B: level histogram + wavefront order (1 block) --------
__global__ void sched_b_kernel() {
    __shared__ int s_start[TN + 1];
    __shared__ int s_cur[TN + 1];
    __shared__ int s_max;
    int i = threadIdx.x;  // 256 threads
    s_cur[i] = 0;
    if (i == 0) { s_max = 0; s_cur[TN] = 0; }
    __syncthreads();
    int L = g_lvl[i];
    atomicMax(&s_max, L);
    atomicAdd(&s_cur[L], 1);
    __syncthreads();
    if (i == 0) {
        int nl = s_max + 1;
        int pos = 0;
        for (int q = 0; q < nl; q++) {
            s_start[q] = pos;
            g_lvlstart[q] = pos;
            pos += s_cur[q];
            s_cur[q] = 0;
        }
        g_lvlstart[nl] = pos;
        g_numlevels = nl;
    }
    __syncthreads();
    int p = atomicAdd(&s_cur[L], 1);
    g_order[s_start[L] + p] = i;
}

// -------- grid barrier --------
__device__ __forceinline__ void grid_sync(unsigned& target) {
    __syncthreads();
    if (threadIdx.x == 0) {
        __threadfence();
        atomicAdd(&g_barcnt, 1u);
        volatile unsigned* p = &g_barcnt;
        while (*p < target) { __nanosleep(32); }
        __threadfence();
    }
    __syncthreads();
    target += gridDim.x;
}

// -------- persistent fused kernel (fp16 2-term, 2-stage pipeline) --------
__global__ __launch_bounds__(256, 2) void persist_kernel(float* __restrict__ hmem) {
    extern __shared__ __align__(16) char dyn[];
    __shared__ int c0s[128];
    __shared__ int c1s[128];
    __shared__ float bcs[NW];
    int tid = threadIdx.x;
    int lane = tid & 31;
    int w = tid >> 5;
    int wm = w >> 1;
    int wn = w & 1;
    int g = lane >> 2;
    int tig = lane & 3;
    unsigned target = gridDim.x;

    uint32_t ubase = smem_u32(dyn);
    int arow = lane & 15;
    int ak8 = (lane >> 4) << 3;
    int bnrow = (lane & 7) + ((lane >> 4) << 3);
    int bk8 = ((lane >> 3) & 1) << 3;
    float* Xs = (float*)dyn;   // exchange buffer: 128*99*4 = 50688 <= DSM

    int nlev = g_numlevels;
    for (int L = 0; L < nlev; L++) {
        int s0 = g_lvlstart[L];
        int ntasks = (g_lvlstart[L + 1] - s0) * 32;
        for (int task = blockIdx.x; task < ntasks; task += gridDim.x) {
            int t = g_order[s0 + (task >> 5)];
            int sub = task & 31;
            int btile = (sub & 3) * 128;
            int ntb = (sub >> 2) * NW;
            int m0 = (sub >> 2) * 32;

            __syncthreads();
            if (tid < 128) {
                c0s[tid] = g_child0[t * BN + btile + tid];
                c1s[tid] = g_child1[t * BN + btile + tid];
            }
            if (tid < NW) bcs[tid] = g_bc[ntb + tid];
            __syncthreads();
            int act = __syncthreads_or((tid < 128) ? ((c0s[tid] >= 0) | (c1s[tid] >= 0)) : 0);
            int nch = act ? (KC / 32) : (INN / 32);

            float d[2][6][4];
            #pragma unroll
            for (int i = 0; i < 2; i++)
                #pragma unroll
                for (int j = 0; j < 6; j++)
                    #pragma unroll
                    for (int q = 0; q < 4; q++) d[i][j][q] = 0.f;

            auto fill = [&](int ch) {
                int kc = ch * 32;
                uint32_t sb = ubase + (uint32_t)(ch & 1) * STG;
                // A hi: 128 rows x 32 k, 8KB -> 512 x 16B ops, 2/thread
                #pragma unroll
                for (int j = 0; j < 2; j++) {
                    int id = tid + j * 256;
                    int row = id >> 2;
                    int seg = id & 3;
                    uint32_t doff = (uint32_t)(row * SP + seg * 8) * 2;
                    const __half* sh;
                    int sz = 16;
                    if (kc < INN) {
                        sh = g_Xhi + ((size_t)t * BN + btile + row) * INN + kc + seg * 8;
                    } else {
                        int c = (kc < INN + MN) ? c0s[row] : c1s[row];
                        size_t o = 0;
                        if (c >= 0) {
                            int col = ((kc - INN) & (MN - 1)) + seg * 8;
                            o = ((size_t)c * BN + btile + row) * MN + col;
                        } else {
                            sz = 0;
                        }
                        sh = g_Hhi + o;
                    }
                    cpa16(sb + doff, sh, sz);
                }
                // B hi + lo: 96 rows x 32 k each
                #pragma unroll
                for (int j = 0; j < 2; j++) {
                    int id = tid + j * 256;
                    if (id < 384) {
                        int row = id >> 2;
                        int seg = id & 3;
                        uint32_t doff = (uint32_t)(row * SP + seg * 8) * 2;
                        size_t o = (size_t)(ntb + row) * KC + kc + seg * 8;
                        cpa16(sb + 10240 + doff, g_Wchi + o, 16);
                        cpa16(sb + 17920 + doff, g_Wclo + o, 16);
                    }
                }
                cpa_commit();
            };

            fill(0);
            for (int ch = 0; ch < nch; ch++) {
                if (ch + 1 < nch) {
                    fill(ch + 1);
                    cpa_wait1();
                } else {
                    cpa_wait0();
                }
                __syncthreads();
                uint32_t sb = ubase + (uint32_t)(ch & 1) * STG;
                uint32_t uA = sb;
                uint32_t uB = sb + 10240;
                uint32_t uBl = sb + 17920;
                #pragma unroll
                for (int s16 = 0; s16 < 2; s16++) {
                    int k0 = s16 * 16;
                    uint32_t ah[2][4];
                    uint32_t bh[3][4];
                    uint32_t bl[3][4];
                    #pragma unroll
                    for (int mt = 0; mt < 2; mt++) {
                        uint32_t off = (uint32_t)(((wm * 32 + mt * 16 + arow) * SP + k0 + ak8) * 2);
                        ldsm4(ah[mt], uA + off);
                    }
                    #pragma unroll
                    for (int p = 0; p < 3; p++) {
                        uint32_t off = (uint32_t)(((wn * 48 + p * 16 + bnrow) * SP + k0 + bk8) * 2);
                        ldsm4(bh[p], uB + off);
                        ldsm4(bl[p], uBl + off);
                    }
                    #pragma unroll
                    for (int mt = 0; mt < 2; mt++) {
                        #pragma unroll
                        for (int p = 0; p < 3; p++) {
                            #pragma unroll
                            for (int q = 0; q < 2; q++) {
                                int nt = p * 2 + q;
                                mma16816(d[mt][nt], ah[mt], &bh[p][q * 2]);
                                mma16816(d[mt][nt], ah[mt], &bl[p][q * 2]);
                            }
                        }
                    }
                }
                __syncthreads();
            }

            // ---- exchange: accum -> smem (stride 99) ----
            #pragma unroll
            for (int mt = 0; mt < 2; mt++) {
                #pragma unroll
                for (int nt = 0; nt < 6; nt++) {
                    int r0 = wm * 32 + mt * 16 + g;
                    int c0 = wn * 48 + nt * 8 + tig * 2;
                    Xs[r0 * 99 + c0] = d[mt][nt][0];
                    Xs[r0 * 99 + c0 + 1] = d[mt][nt][1];
                    Xs[(r0 + 8) * 99 + c0] = d[mt][nt][2];
                    Xs[(r0 + 8) * 99 + c0 + 1] = d[mt][nt][3];
                }
            }
            __syncthreads();

            // ---- fused LSTM epilogue (fast math) ----
            {
                int row = tid >> 1;
                int mh = (tid & 1) * 16;
                float hv[16];
                #pragma unroll
                for (int mm = 0; mm < 16; mm++) {
                    int mj = mh + mm;
                    float vi = Xs[row * 99 + mj * 3 + 0] + bcs[mj * 3 + 0];
                    float vo = Xs[row * 99 + mj * 3 + 1] + bcs[mj * 3 + 1];
                    float vu = Xs[row * 99 + mj * 3 + 2] + bcs[mj * 3 + 2];
                    float cc = sigf(vi) * tanhfast(vu);
                    hv[mm] = sigf(vo) * tanhfast(cc);
                }
                size_t base = ((size_t)t * BN + btile + row) * MN + m0 + mh;
                #pragma unroll
                for (int q = 0; q < 4; q++) {
                    *(float4*)(hmem + base + q * 4) =
                        make_float4(hv[q * 4], hv[q * 4 + 1], hv[q * 4 + 2], hv[q * 4 + 3]);
                }
                uint32_t ph[8];
                #pragma unroll
                for (int q = 0; q < 8; q++) {
                    ph[q] = packh2(hv[q * 2], hv[q * 2 + 1]);
                }
                *(uint4*)(g_Hhi + base) = make_uint4(ph[0], ph[1], ph[2], ph[3]);
                *(uint4*)(g_Hhi + base + 8) = make_uint4(ph[4], ph[5], ph[6], ph[7]);
            }
        }
        grid_sync(target);
    }
}

// -------- root gather --------
__global__ void root_kernel(float* __restrict__ out, const float* __restrict__ hmem) {
    int b = blockIdx.x;
    int m = threadIdx.x;
    out[b * MN + m] = hmem[((size_t)g_root[b] * BN + b) * MN + m];
}

extern "C" void kernel_launch(void* const* d_in, const int* in_sizes, int n_in,
                              void* d_out, int out_size) {
    const float* X  = (const float*)d_in[0];
    const int*   ar = (const int*)  d_in[1];
    const float* Wi = (const float*)d_in[2];
    const float* bi = (const float*)d_in[3];
    const float* Wo = (const float*)d_in[4];
    const float* bo = (const float*)d_in[5];
    const float* Wu = (const float*)d_in[6];
    const float* bu = (const float*)d_in[7];
    const float* Ui = (const float*)d_in[10];
    const float* Uo = (const float*)d_in[11];
    const float* Uu = (const float*)d_in[12];

    float* out  = (float*)d_out;
    float* hmem = out + BN * MN;

    cudaFuncSetAttribute(persist_kernel, cudaFuncAttributeMaxDynamicSharedMemorySize, DSM);

    prep_kernel<<<512, 256>>>(X, Wi, bi, Wo, bo, Wu, bu, Ui, Uo, Uu);
    sched_a_kernel<<<16, 32>>>(ar);
    sched_b_kernel<<<1, 256>>>();
    persist_kernel<<<GRID_P, 256, DSM>>>(hmem);
    root_kernel<<<BN, MN>>>(out, hmem);
}

// round 14
// speedup vs baseline: 1.1992x; 1.1992x over previous
#include <cuda_runtime.h>
#include <cuda_bf16.h>
#include <math.h>
#include <stdint.h>

#define TN  256
#define BN  512
#define INN 128
#define MN  256
#define KC  640          // fused K: 128 x + 2*256 children
#define NW  96           // N tile: 32 m * 3 gates (permuted slot layout)
#define GRID_P 296
#define SP  40           // padded smem row stride (bf16)

// dynamic smem: 2 stages * 35840B; stage: Ahi 0, Alo 10240, Bhi 20480, Blo 28160
#define STG 35840
#define DSM (2 * STG)

// -------- device scratch --------
__device__ __nv_bfloat16 g_Wchi[768 * KC];   // fused weights, permuted slots [n'][k]
__device__ __nv_bfloat16 g_Wclo[768 * KC];
__device__ __nv_bfloat16 g_Xhi[(size_t)TN * BN * INN];
__device__ __nv_bfloat16 g_Xlo[(size_t)TN * BN * INN];
__device__ __nv_bfloat16 g_Hhi[(size_t)TN * BN * MN];
__device__ __nv_bfloat16 g_Hlo[(size_t)TN * BN * MN];
__device__ float g_bc[768];                  // bias, same permuted slot order
__device__ int   g_child0[TN * BN];
__device__ int   g_child1[TN * BN];
__device__ int   g_root[BN];
__device__ int   g_order[TN];
__device__ int   g_lvl[TN];
__device__ int   g_lvlstart[TN + 2];
__device__ int   g_numlevels;
__device__ unsigned g_barcnt;

// fast sigmoid / tanh via MUFU. rel err ~1e-6.
__device__ __forceinline__ float sigf(float x) {
    return __fdividef(1.0f, 1.0f + __expf(-x));
}
__device__ __forceinline__ float tanhfast(float x) {
    return 2.0f * __fdividef(1.0f, 1.0f + __expf(-2.0f * x)) - 1.0f;
}

__device__ __forceinline__ uint32_t smem_u32(const void* p) {
    uint32_t a;
    asm("{ .reg .u64 t; cvta.to.shared.u64 t, %1; cvt.u32.u64 %0, t; }" : "=r"(a) : "l"(p));
    return a;
}

__device__ __forceinline__ void mma16816(float* d, const uint32_t* a, const uint32_t* b) {
    asm volatile(
        "mma.sync.aligned.m16n8k16.row.col.f32.bf16.bf16.f32 "
        "{%0,%1,%2,%3}, {%4,%5,%6,%7}, {%8,%9}, {%0,%1,%2,%3};"
        : "+f"(d[0]), "+f"(d[1]), "+f"(d[2]), "+f"(d[3])
        : "r"(a[0]), "r"(a[1]), "r"(a[2]), "r"(a[3]), "r"(b[0]), "r"(b[1]));
}

__device__ __forceinline__ void ldsm4(uint32_t* r, uint32_t addr) {
    asm volatile("ldmatrix.sync.aligned.m8n8.x4.shared.b16 {%0,%1,%2,%3}, [%4];"
                 : "=r"(r[0]), "=r"(r[1]), "=r"(r[2]), "=r"(r[3]) : "r"(addr));
}

__device__ __forceinline__ void cpa16(uint32_t dst, const void* src, int sz) {
    asm volatile("cp.async.ca.shared.global [%0], [%1], 16, %2;"
                 :: "r"(dst), "l"(src), "r"(sz) : "memory");
}
__device__ __forceinline__ void cpa_commit() {
    asm volatile("cp.async.commit_group;" ::: "memory");
}
__device__ __forceinline__ void cpa_wait1() {
    asm volatile("cp.async.wait_group 1;" ::: "memory");
}
__device__ __forceinline__ void cpa_wait0() {
    asm volatile("cp.async.wait_group 0;" ::: "memory");
}

__device__ __forceinline__ uint32_t packbf2(float x, float y) {
    __nv_bfloat162 v = __floats2bfloat162_rn(x, y);
    return *reinterpret_cast<uint32_t*>(&v);
}

// slot permutation: within each 96-col tile, slot s -> (gate, m_local32)
//   w48 = s/48, s48 = s%48, nt = s48>>3, rem = s48&7, tg = rem>>1, e = rem&1
//   gate = nt>>1, m_local = w48*16 + tg*4 + (nt&1)*2 + e
// This makes each MMA thread (tig=tg) own complete gate triples -> register epilogue.

// -------- prep: X split, permuted fused weights, bias, sched init --------
__global__ void prep_kernel(const float* __restrict__ X,
                            const float* __restrict__ Wi, const float* __restrict__ bi,
                            const float* __restrict__ Wo, const float* __restrict__ bo,
                            const float* __restrict__ Wu, const float* __restrict__ bu,
                            const float* __restrict__ Ui, const float* __restrict__ Uo,
                            const float* __restrict__ Uu) {
    size_t idx = blockIdx.x * blockDim.x + threadIdx.x;
    size_t stride = (size_t)gridDim.x * blockDim.x;
    if (idx == 0) g_barcnt = 0u;
    for (size_t i = idx; i < TN; i += stride) g_lvl[i] = 0;
    for (size_t i = idx; i < (size_t)TN * BN * INN; i += stride) {
        float x = X[i];
        __nv_bfloat16 h = __float2bfloat16_rn(x);
        g_Xhi[i] = h;
        g_Xlo[i] = __float2bfloat16_rn(x - __bfloat162float(h));
    }
    for (size_t i = idx; i < (size_t)768 * KC; i += stride) {
        int n = (int)(i / KC);
        int k = (int)(i % KC);
        int tile = n / 96;
        int s = n % 96;
        int w48 = s / 48;
        int s48 = s % 48;
        int nt = s48 >> 3;
        int rem = s48 & 7;
        int tg = rem >> 1;
        int e = rem & 1;
        int g = nt >> 1;
        int m = tile * 32 + w48 * 16 + tg * 4 + (nt & 1) * 2 + e;
        float x;
        if (k < INN) {
            const float* W = (g == 0) ? Wi : ((g == 1) ? Wo : Wu);
            x = W[m * INN + k];
        } else {
            const float* U = (g == 0) ? Ui : ((g == 1) ? Uo : Uu);
            int br = (k - INN) / MN;
            int kk = (k - INN) % MN;
            x = U[br * MN * MN + m * MN + kk];
        }
        __nv_bfloat16 h = __float2bfloat16_rn(x);
        g_Wchi[i] = h;
        g_Wclo[i] = __float2bfloat16_rn(x - __bfloat162float(h));
    }
    for (size_t i = idx; i < 768; i += stride) {
        int n = (int)i;
        int tile = n / 96;
        int s = n % 96;
        int w48 = s / 48;
        int s48 = s % 48;
        int nt = s48 >> 3;
        int rem = s48 & 7;
        int tg = rem >> 1;
        int e = rem & 1;
        int g = nt >> 1;
        int m = tile * 32 + w48 * 16 + tg * 4 + (nt & 1) * 2 + e;
        const float* bb = (g == 0) ? bi : ((g == 1) ? bo : bu);
        g_bc[n] = bb[m];
    }
}

// -------- scheduler A: per-tree stack sim, 16 blocks x 32 trees --------
__global__ void sched_a_kernel(const int* __restrict__ arities) {
    int b = blockIdx.x * 32 + threadIdx.x;
    int stck[TN + 2];
    int lvl[TN];
    for (int i = 0; i < TN + 2; i++) stck[i] = 0;
    int sp = 1;
    for (int t = 0; t < TN; t++) {
        int a = arities[t * BN + b];
        int c0 = -1;
        int c1 = -1;
        if (a > 0) {
            int s = stck[max(sp, 0)];
            if (s < t) c0 = s;
        }
        if (a > 1) {
            int s = stck[max(sp - 1, 0)];
            if (s < t) c1 = s;
        }
        g_child0[t * BN + b] = c0;
        g_child1[t * BN + b] = c1;
        int L = 0;
        if (c0 >= 0) L = lvl[c0] + 1;
        if (c1 >= 0) L = max(L, lvl[c1] + 1);
        lvl[t] = L;
        atomicMax(&g_lvl[t], L);
        sp += 1 - abs(a);
        if (sp < 0) sp = 0;
        if (sp > TN + 1) sp = TN + 1;
        if (a != -1) stck[sp] = t;
    }
    g_root[b] = stck[max(sp, 0)];
}

// -------- scheduler B: level histogram + wavefront order (1 block) --------
__global__ void sched_b_kernel() {
    __shared__ int s_start[TN + 1];
    __shared__ int s_cur[TN + 1];
    __shared__ int s_max;
    int i = threadIdx.x;  // 256 threads
    s_cur[i] = 0;
    if (i == 0) { s_max = 0; s_cur[TN] = 0; }
    __syncthreads();
    int L = g_lvl[i];
    atomicMax(&s_max, L);
    atomicAdd(&s_cur[L], 1);
    __syncthreads();
    if (i == 0) {
        int nl = s_max + 1;
        int pos = 0;
        for (int q = 0; q < nl; q++) {
            s_start[q] = pos;
            g_lvlstart[q] = pos;
            pos += s_cur[q];
            s_cur[q] = 0;
        }
        g_lvlstart[nl] = pos;
        g_numlevels = nl;
    }
    __syncthreads();
    int p = atomicAdd(&s_cur[L], 1);
    g_order[s_start[L] + p] = i;
}

// -------- grid barrier --------
__device__ __forceinline__ void grid_sync(unsigned& target) {
    __syncthreads();
    if (threadIdx.x == 0) {
        __threadfence();
        atomicAdd(&g_barcnt, 1u);
        volatile unsigned* p = &g_barcnt;
        while (*p < target) { __nanosleep(32); }
        __threadfence();
    }
    __syncthreads();
    target += gridDim.x;
}

// -------- persistent fused kernel (bf16 3-term, register epilogue) --------
__global__ __launch_bounds__(256, 2) void persist_kernel(float* __restrict__ hmem) {
    extern __shared__ __align__(16) char dyn[];
    __shared__ int c0s[128];
    __shared__ int c1s[128];
    __shared__ float bcs[NW];
    int tid = threadIdx.x;
    int lane = tid & 31;
    int w = tid >> 5;
    int wm = w >> 1;
    int wn = w & 1;
    int g = lane >> 2;
    int tig = lane & 3;
    unsigned target = gridDim.x;

    uint32_t ubase = smem_u32(dyn);
    int arow = lane & 15;
    int ak8 = (lane >> 4) << 3;
    int bnrow = (lane & 7) + ((lane >> 4) << 3);
    int bk8 = ((lane >> 3) & 1) << 3;

    int nlev = g_numlevels;
    for (int L = 0; L < nlev; L++) {
        int s0 = g_lvlstart[L];
        int ntasks = (g_lvlstart[L + 1] - s0) * 32;
        for (int task = blockIdx.x; task < ntasks; task += gridDim.x) {
            int t = g_order[s0 + (task >> 5)];
            int sub = task & 31;
            int btile = (sub & 3) * 128;
            int ntb = (sub >> 2) * NW;
            int m0 = (sub >> 2) * 32;

            // single boundary barrier: syncthreads_or below. Previous-task readers of
            // c0s/bcs all finished before the last in-loop __syncthreads.
            if (tid < 128) {
                c0s[tid] = g_child0[t * BN + btile + tid];
                c1s[tid] = g_child1[t * BN + btile + tid];
            }
            if (tid < NW) bcs[tid] = g_bc[ntb + tid];
            int act = __syncthreads_or((tid < 128) ? ((c0s[tid] >= 0) | (c1s[tid] >= 0)) : 0);
            int nch = act ? (KC / 32) : (INN / 32);

            float d[2][6][4];
            #pragma unroll
            for (int i = 0; i < 2; i++)
                #pragma unroll
                for (int j = 0; j < 6; j++)
                    #pragma unroll
                    for (int q = 0; q < 4; q++) d[i][j][q] = 0.f;

            auto fill = [&](int ch) {
                int kc = ch * 32;
                uint32_t sb = ubase + (uint32_t)(ch & 1) * STG;
                #pragma unroll
                for (int j = 0; j < 2; j++) {
                    int id = tid + j * 256;
                    int row = id >> 2;
                    int seg = id & 3;
                    uint32_t doff = (uint32_t)(row * SP + seg * 8) * 2;
                    const __nv_bfloat16* sh;
                    const __nv_bfloat16* sl;
                    int sz = 16;
                    if (kc < INN) {
                        size_t o = ((size_t)t * BN + btile + row) * INN + kc + seg * 8;
                        sh = g_Xhi + o;
                        sl = g_Xlo + o;
                    } else {
                        int c = (kc < INN + MN) ? c0s[row] : c1s[row];
                        size_t o = 0;
                        if (c >= 0) {
                            int col = ((kc - INN) & (MN - 1)) + seg * 8;
                            o = ((size_t)c * BN + btile + row) * MN + col;
                        } else {
                            sz = 0;
                        }
                        sh = g_Hhi + o;
                        sl = g_Hlo + o;
                    }
                    cpa16(sb + doff, sh, sz);
                    cpa16(sb + 10240 + doff, sl, sz);
                }
                #pragma unroll
                for (int j = 0; j < 2; j++) {
                    int id = tid + j * 256;
                    if (id < 384) {
                        int row = id >> 2;
                        int seg = id & 3;
                        uint32_t doff = (uint32_t)(row * SP + seg * 8) * 2;
                        size_t o = (size_t)(ntb + row) * KC + kc + seg * 8;
                        cpa16(sb + 20480 + doff, g_Wchi + o, 16);
                        cpa16(sb + 28160 + doff, g_Wclo + o, 16);
                    }
                }
                cpa_commit();
            };

            fill(0);
            for (int ch = 0; ch < nch; ch++) {
                if (ch + 1 < nch) {
                    fill(ch + 1);
                    cpa_wait1();
                } else {
                    cpa_wait0();
                }
                __syncthreads();
                uint32_t sb = ubase + (uint32_t)(ch & 1) * STG;
                uint32_t uA = sb;
                uint32_t uAl = sb + 10240;
                uint32_t uB = sb + 20480;
                uint32_t uBl = sb + 28160;
                #pragma unroll
                for (int s16 = 0; s16 < 2; s16++) {
                    int k0 = s16 * 16;
                    uint32_t ah[2][4];
                    uint32_t al[2][4];
                    uint32_t bh[3][4];
                    uint32_t bl[3][4];
                    #pragma unroll
                    for (int mt = 0; mt < 2; mt++) {
                        uint32_t off = (uint32_t)(((wm * 32 + mt * 16 + arow) * SP + k0 + ak8) * 2);
                        ldsm4(ah[mt], uA + off);
                        ldsm4(al[mt], uAl + off);
                    }
                    #pragma unroll
                    for (int p = 0; p < 3; p++) {
                        uint32_t off = (uint32_t)(((wn * 48 + p * 16 + bnrow) * SP + k0 + bk8) * 2);
                        ldsm4(bh[p], uB + off);
                        ldsm4(bl[p], uBl + off);
                    }
                    #pragma unroll
                    for (int mt = 0; mt < 2; mt++) {
                        #pragma unroll
                        for (int p = 0; p < 3; p++) {
                            #pragma unroll
                            for (int q = 0; q < 2; q++) {
                                int nt = p * 2 + q;
                                mma16816(d[mt][nt], ah[mt], &bh[p][q * 2]);
                                mma16816(d[mt][nt], ah[mt], &bl[p][q * 2]);
                                mma16816(d[mt][nt], al[mt], &bh[p][q * 2]);
                            }
                        }
                    }
                }
                __syncthreads();
            }

            // ---- register LSTM epilogue (permuted slots => gate triples in-thread) ----
            // accum d[mt][nt][q]: rows wm*32+mt*16+g+8*(q>>1), slot wn*48+nt*8+tig*2+(q&1)
            // gate = nt>>1; m_idx = (nt&1)*2 + (q&1); m_global = m0+wn*16+tig*4+m_idx
            {
                int mbase = m0 + wn * 16 + tig * 4;
                int sbase = wn * 48 + tig * 2;
                #pragma unroll
                for (int mt = 0; mt < 2; mt++) {
                    #pragma unroll
                    for (int rt = 0; rt < 2; rt++) {
                        int row = btile + wm * 32 + mt * 16 + g + rt * 8;
                        float hv[4];
                        #pragma unroll
                        for (int mi = 0; mi < 4; mi++) {
                            int a = mi >> 1;       // nt offset within gate group
                            int e = mi & 1;
                            int q = rt * 2 + e;
                            float vi = d[mt][a][q]     + bcs[sbase + a * 8 + e];
                            float vo = d[mt][2 + a][q] + bcs[sbase + 16 + a * 8 + e];
                            float vu = d[mt][4 + a][q] + bcs[sbase + 32 + a * 8 + e];
                            float cc = sigf(vi) * tanhfast(vu);
                            hv[mi] = sigf(vo) * tanhfast(cc);
                        }
                        size_t base = ((size_t)t * BN + row) * MN + mbase;
                        *(float4*)(hmem + base) = make_float4(hv[0], hv[1], hv[2], hv[3]);
                        uint32_t p0;
                        uint32_t p1;
                        uint32_t l0;
                        uint32_t l1;
                        {
                            __nv_bfloat16 b0 = __float2bfloat16_rn(hv[0]);
                            __nv_bfloat16 b1 = __float2bfloat16_rn(hv[1]);
                            __nv_bfloat16 b2 = __float2bfloat16_rn(hv[2]);
                            __nv_bfloat16 b3 = __float2bfloat16_rn(hv[3]);
                            float f0 = __bfloat162float(b0);
                            float f1 = __bfloat162float(b1);
                            float f2 = __bfloat162float(b2);
                            float f3 = __bfloat162float(b3);
                            p0 = packbf2(f0, f1);
                            p1 = packbf2(f2, f3);
                            l0 = packbf2(hv[0] - f0, hv[1] - f1);
                            l1 = packbf2(hv[2] - f2, hv[3] - f3);
                        }
                        *(uint2*)(g_Hhi + base) = make_uint2(p0, p1);
                        *(uint2*)(g_Hlo + base) = make_uint2(l0, l1);
                    }
                }
            }
        }
        grid_sync(target);
    }
}

// -------- root gather --------
__global__ void root_kernel(float* __restrict__ out, const float* __restrict__ hmem) {
    int b = blockIdx.x;
    int m = threadIdx.x;
    out[b * MN + m] = hmem[((size_t)g_root[b] * BN + b) * MN + m];
}

extern "C" void kernel_launch(void* const* d_in, const int* in_sizes, int n_in,
                              void* d_out, int out_size) {
    const float* X  = (const float*)d_in[0];
    const int*   ar = (const int*)  d_in[1];
    const float* Wi = (const float*)d_in[2];
    const float* bi = (const float*)d_in[3];
    const float* Wo = (const float*)d_in[4];
    const float* bo = (const float*)d_in[5];
    const float* Wu = (const float*)d_in[6];
    const float* bu = (const float*)d_in[7];
    const float* Ui = (const float*)d_in[10];
    const float* Uo = (const float*)d_in[11];
    const float* Uu = (const float*)d_in[12];

    float* out  = (float*)d_out;
    float* hmem = out + BN * MN;

    cudaFuncSetAttribute(persist_kernel, cudaFuncAttributeMaxDynamicSharedMemorySize, DSM);

    prep_kernel<<<512, 256>>>(X, Wi, bi, Wo, bo, Wu, bu, Ui, Uo, Uu);
    sched_a_kernel<<<16, 32>>>(ar);
    sched_b_kernel<<<1, 256>>>();
    persist_kernel<<<GRID_P, 256, DSM>>>(hmem);
    root_kernel<<<BN, MN>>>(out, hmem);
}